// round 6
// baseline (speedup 1.0000x reference)
#include <cuda_runtime.h>

#define NC 128
#define EPS 1e-5f
#define RAYS_PER_CTA 8          // 8 warps/CTA, one ray per warp
#define THREADS (RAYS_PER_CTA * 32)

__global__ __launch_bounds__(THREADS) void pdf_sampler_kernel(
    const float* __restrict__ deltas,
    const float* __restrict__ density,
    const float* __restrict__ bins,
    const float* __restrict__ u,
    float* __restrict__ out)
{
    const int lane = threadIdx.x & 31;
    const int wrp  = threadIdx.x >> 5;
    const int ray  = blockIdx.x * RAYS_PER_CTA + wrp;

    // cd[i] = cdf[i+1] for i=0..127; cd[128] = cdf[128] dummy (kills c1 clamp)
    __shared__ __align__(16) float cdfv_sh[RAYS_PER_CTA][132];
    // bins[0..128]; [129] = bins[128] dummy (kills b1 clamp)
    __shared__ __align__(16) float bins_sh[RAYS_PER_CTA][132];

    const size_t base_c = (size_t)ray * NC;

    // ---- coalesced loads (full bins row NOT loaded; only near) ----
    const float4 dv = *(const float4*)(deltas  + base_c + 4 * lane);
    const float4 rv = *(const float4*)(density + base_c + 4 * lane);
    const float4 uv = *(const float4*)(u       + base_c + 4 * lane);
    const float nearv = bins[(size_t)ray * (NC + 1)];   // warp-uniform

    // ---- per-lane serial prefixes: dd = delta*density, and delta ----
    const float dd0 = dv.x * rv.x;
    const float dd1 = dv.y * rv.y;
    const float dd2 = dv.z * rv.z;
    const float dd3 = dv.w * rv.w;
    const float pA0 = dd0, pA1 = pA0 + dd1, pA2 = pA1 + dd2, pA3 = pA2 + dd3;
    const float pD0 = dv.x, pD1 = pD0 + dv.y, pD2 = pD1 + dv.z, pD3 = pD2 + dv.w;

    // ---- fused dual warp scan over lane totals ----
    float sA = pA3, sD = pD3;
    #pragma unroll
    for (int o = 1; o < 32; o <<= 1) {
        const float nA = __shfl_up_sync(0xffffffffu, sA, o);
        const float nD = __shfl_up_sync(0xffffffffu, sD, o);
        if (lane >= o) { sA += nA; sD += nD; }
    }
    const float offA = sA - pA3;      // exclusive dd-cumsum at element e
    const float offD = sD - pD3;      // exclusive delta-cumsum at element e

    // ---- telescoped cdf: cumsum(w)[i] = 1 - exp(-cumsum(dd)[i]) ----
    const float total = __shfl_sync(0xffffffffu, sA, 31);
    const float wsum  = 1.0f - __expf(-total);
    const float pad   = fmaxf(EPS - wsum, 0.0f);
    const float inv   = __fdividef(1.0f, wsum + pad);
    const float ps    = pad * (1.0f / (float)NC);

    const int e = 4 * lane;
    float4 cv;
    cv.x = fminf(1.0f, (1.0f - __expf(-(offA + pA0)) + ps * (float)(e + 1)) * inv);
    cv.y = fminf(1.0f, (1.0f - __expf(-(offA + pA1)) + ps * (float)(e + 2)) * inv);
    cv.z = fminf(1.0f, (1.0f - __expf(-(offA + pA2)) + ps * (float)(e + 3)) * inv);
    cv.w = fminf(1.0f, (1.0f - __expf(-(offA + pA3)) + ps * (float)(e + 4)) * inv);
    *(float4*)(&cdfv_sh[wrp][e]) = cv;            // aligned, conflict-free

    // ---- reconstruct bins[e..e+4]; one STS.128 ----
    const float be0 = nearv + offD;
    *(float4*)(&bins_sh[wrp][e]) =
        make_float4(be0, be0 + pD0, be0 + pD1, be0 + pD2);
    if (lane == 31) {
        const float blast = be0 + pD3;            // bins[128]
        bins_sh[wrp][NC]     = blast;
        bins_sh[wrp][NC + 1] = blast;             // dummy
        cdfv_sh[wrp][NC]     = cv.w;              // cd[128] = cdf[128] dummy
    }

    __syncwarp();

    const float* __restrict__ cd = cdfv_sh[wrp];
    const float* __restrict__ bn = bins_sh[wrp];

    // hoisted level-1/2 probe values (broadcast loads, reused by all 4 samples)
    const float g64 = cd[63];    // cdf[64]
    const float g32 = cd[31];    // cdf[32]
    const float g96 = cd[95];    // cdf[96]

    float4 res;

    #pragma unroll
    for (int i = 0; i < 4; i++) {
        const float uu = (i == 0) ? uv.x : (i == 1) ? uv.y : (i == 2) ? uv.z : uv.w;

        // pos = #{cd[k] <= u} over cd[0..127]
        int pos = 0;
        const bool l1 = (g64 <= uu);
        if (l1) pos = 64;
        const float v2 = l1 ? g96 : g32;
        if (v2 <= uu) pos += 32;
        #pragma unroll
        for (int step = 16; step >= 1; step >>= 1) {
            if (cd[pos + step - 1] <= uu) pos += step;
        }

        const float c0 = (pos == 0) ? 0.0f : cd[pos - 1];
        const float c1 = cd[pos];          // pos<=128 valid via dummy
        const float b0 = bn[pos];
        const float b1 = bn[pos + 1];      // <=129 valid via dummy

        float den = c1 - c0;
        den = (den < EPS) ? 1.0f : den;
        const float frac = __fdividef(uu - c0, den);
        const float s = b0 + frac * (b1 - b0);
        if (i == 0) res.x = s; else if (i == 1) res.y = s; else if (i == 2) res.z = s; else res.w = s;
    }

    *(float4*)(out + base_c + 4 * lane) = res;
}

extern "C" void kernel_launch(void* const* d_in, const int* in_sizes, int n_in,
                              void* d_out, int out_size) {
    const float* deltas  = (const float*)d_in[0];
    const float* density = (const float*)d_in[1];
    const float* bins    = (const float*)d_in[2];
    const float* u       = (const float*)d_in[3];
    float* out = (float*)d_out;

    int R = in_sizes[0] / NC;               // 131072
    pdf_sampler_kernel<<<R / RAYS_PER_CTA, THREADS>>>(deltas, density, bins, u, out);
}